// round 4
// baseline (speedup 1.0000x reference)
#include <cuda_runtime.h>

// SlidingGaussianWindow1d: out[b,w,c,d] = clip(corrcoef over t of x[b,t,:] * W[w,t])
// B=16, T=256, C=64, NWIN=224.
//
// Key identities used:
//  - W[w,t] = A[(t + S_w) mod 256], S_w = cumsum(k-111) = (w+1)(w-222)/2
//  - A independent of win_alpha up to exact normalization (still computed on device)
//  - cov_cd = (sum_t y_c y_d - m_c m_d / T) / (T-1), y = x*W, m_c = sum_t y_c

#define T_LEN 256
#define C_DIM 64
#define NWIN  224
#define B_DIM 16

__device__ float g_A[256];  // normalized, cropped smoothed-box window

// ---------------------------------------------------------------------------
// Prep: compute A[t] from win_alpha. gw = exp(-(t-128)^2)/(2a^2);
// Aconv = full conv(gw, box[112:144]); normalize by global max; crop [128:384].
// ---------------------------------------------------------------------------
__global__ void prep_kernel(const float* __restrict__ alpha) {
    __shared__ float gw[256];
    __shared__ float Ac[511];
    __shared__ float red[64];
    __shared__ float s_max;
    int tid = threadIdx.x;  // 512 threads

    float a = alpha[0];
    float inv = 1.0f / (2.0f * a * a);
    if (tid < 256) {
        float d = (float)tid - 128.0f;
        gw[tid] = expf(-d * d) * inv;
    }
    __syncthreads();
    if (tid < 511) {
        // conv(gw, b)[n] = sum_{k=n-143}^{n-112} gw[k]  (box nonzero on [112,144))
        int lo = tid - 143; if (lo < 0)   lo = 0;
        int hi = tid - 112; if (hi > 255) hi = 255;
        float s = 0.0f;
        for (int k = lo; k <= hi; k++) s += gw[k];
        Ac[tid] = s;
    }
    __syncthreads();
    if (tid < 64) {
        float m = 0.0f;
        for (int n = tid; n < 511; n += 64) m = fmaxf(m, Ac[n]);
        red[tid] = m;
    }
    __syncthreads();
    if (tid == 0) {
        float m = 0.0f;
        #pragma unroll
        for (int n = 0; n < 64; n++) m = fmaxf(m, red[n]);
        s_max = m;
    }
    __syncthreads();
    if (tid < 256) g_A[tid] = Ac[128 + tid] / s_max;
}

// ---------------------------------------------------------------------------
// Main: one CTA per (w, b). 256 threads = 4 K-groups x 64 threads; each thread
// owns an 8x8 (c,d) output tile over its K-slice (t = g, g+4, ...).
// smem: y[256][64] fp32 (64 KB dynamic), reused as 4x4096 reduction buffer.
// ---------------------------------------------------------------------------
__global__ __launch_bounds__(256) void corr_kernel(const float* __restrict__ x,
                                                   float* __restrict__ out) {
    extern __shared__ float sm[];        // 16384 floats = 64 KB
    __shared__ float mpart[4][64];
    __shared__ float mcol[64];
    __shared__ float dinv[64];

    const int w = blockIdx.x;
    const int b = blockIdx.y;
    const int tid = threadIdx.x;

    // cumulative roll: S_w = (w+1)(w-222)/2 (always even product -> exact)
    int s = ((w + 1) * (w - 222)) / 2;
    int smod = s % 256; if (smod < 0) smod += 256;

    // ---- load x[b] and scale by rolled window -> y in smem (coalesced) ----
    const float4* x4 = (const float4*)(x + (size_t)b * (T_LEN * C_DIM));
    #pragma unroll
    for (int k = 0; k < 16; k++) {
        int i4 = tid + (k << 8);         // 0..4095 float4s
        int t = i4 >> 4;                 // 16 float4 per row of 64 floats
        float aw = g_A[(t + smod) & 255];
        float4 v = x4[i4];
        v.x *= aw; v.y *= aw; v.z *= aw; v.w *= aw;
        ((float4*)sm)[i4] = v;
    }
    __syncthreads();

    // ---- column sums m_c = sum_t y[t][c], 4-way split over t ----
    {
        int c = tid & 63;
        int q = tid >> 6;
        const float* p = sm + (q << 12) + c;   // rows [q*64, q*64+64)
        float ssum = 0.0f;
        #pragma unroll 8
        for (int t = 0; t < 64; t++) ssum += p[t * 64];
        mpart[q][c] = ssum;
    }
    __syncthreads();
    if (tid < 64) mcol[tid] = mpart[0][tid] + mpart[1][tid] + mpart[2][tid] + mpart[3][tid];
    // (no barrier needed: mcol only read after the post-mainloop barrier)

    // ---- main accumulation: S_cd = sum_t y_c y_d ----
    const int g   = tid >> 6;            // K-group 0..3
    const int l   = tid & 63;
    const int ci0 = (l & 7) << 3;        // c tile base
    const int dj0 = (l >> 3) << 3;       // d tile base

    float acc[64];
    #pragma unroll
    for (int k = 0; k < 64; k++) acc[k] = 0.0f;

    #pragma unroll 2
    for (int t = g; t < 256; t += 4) {
        const float* row = sm + (t << 6);
        float4 a0 = *(const float4*)(row + ci0);
        float4 a1 = *(const float4*)(row + ci0 + 4);
        float4 b0 = *(const float4*)(row + dj0);
        float4 b1 = *(const float4*)(row + dj0 + 4);
        float ac[8] = {a0.x, a0.y, a0.z, a0.w, a1.x, a1.y, a1.z, a1.w};
        float bd[8] = {b0.x, b0.y, b0.z, b0.w, b1.x, b1.y, b1.z, b1.w};
        #pragma unroll
        for (int ci = 0; ci < 8; ci++)
            #pragma unroll
            for (int dj = 0; dj < 8; dj++)
                acc[ci * 8 + dj] = fmaf(ac[ci], bd[dj], acc[ci * 8 + dj]);
    }
    __syncthreads();                     // y no longer needed; reuse smem

    // ---- publish 4 partial 64x64 tiles ----
    {
        float* red = sm + (g << 12);
        #pragma unroll
        for (int ci = 0; ci < 8; ci++)
            #pragma unroll
            for (int dj = 0; dj < 8; dj++)
                red[(ci0 + ci) * 64 + (dj0 + dj)] = acc[ci * 8 + dj];
    }
    __syncthreads();

    // ---- combine partials, covariance, store cov in smem[0:4096) ----
    const float inv256 = 1.0f / 256.0f;
    const float inv255 = 1.0f / 255.0f;
    const int cd0 = tid << 4;            // each thread owns 16 consecutive cd
    float covv[16];
    #pragma unroll
    for (int k = 0; k < 16; k++) {
        int cd = cd0 + k;
        float ssum = sm[cd] + sm[4096 + cd] + sm[8192 + cd] + sm[12288 + cd];
        int c  = cd >> 6;
        int d2 = cd & 63;
        covv[k] = (ssum - mcol[c] * mcol[d2] * inv256) * inv255;
    }
    #pragma unroll
    for (int k = 0; k < 16; k++) sm[cd0 + k] = covv[k];  // each cd has one owner
    __syncthreads();

    if (tid < 64) dinv[tid] = rsqrtf(sm[tid * 65]);      // diag cd = c*64+c
    __syncthreads();

    // ---- normalize, clip, write out (float4, coalesced) ----
    float4* ob = (float4*)(out + ((size_t)(b * NWIN + w) << 12));
    float dc = dinv[tid >> 2];           // c = cd0/64 fixed within thread's 16
    #pragma unroll
    for (int k4 = 0; k4 < 4; k4++) {
        int base = cd0 + (k4 << 2);
        float4 o;
        o.x = sm[base + 0] * dc * dinv[(base + 0) & 63];
        o.y = sm[base + 1] * dc * dinv[(base + 1) & 63];
        o.z = sm[base + 2] * dc * dinv[(base + 2) & 63];
        o.w = sm[base + 3] * dc * dinv[(base + 3) & 63];
        o.x = fminf(1.0f, fmaxf(-1.0f, o.x));
        o.y = fminf(1.0f, fmaxf(-1.0f, o.y));
        o.z = fminf(1.0f, fmaxf(-1.0f, o.z));
        o.w = fminf(1.0f, fmaxf(-1.0f, o.w));
        ob[(tid << 2) + k4] = o;
    }
}

// ---------------------------------------------------------------------------
extern "C" void kernel_launch(void* const* d_in, const int* in_sizes, int n_in,
                              void* d_out, int out_size) {
    const float* x     = (const float*)d_in[0];   // (16, 256, 64) fp32
    const float* alpha = (const float*)d_in[1];   // (1,) fp32
    float* out = (float*)d_out;                   // (16, 224, 64, 64) fp32

    cudaFuncSetAttribute(corr_kernel,
                         cudaFuncAttributeMaxDynamicSharedMemorySize, 65536);

    prep_kernel<<<1, 512>>>(alpha);
    dim3 grid(NWIN, B_DIM);
    corr_kernel<<<grid, 256, 65536>>>(x, out);
}

// round 6
// speedup vs baseline: 6.8159x; 6.8159x over previous
#include <cuda_runtime.h>
#include <cstdint>

// SlidingGaussianWindow1d: out[b,w,c,d] = clip(corrcoef_t of x[b,t,:] * W[w,t])
// B=16, T=256, C=64, NWIN=224.
//
// Identities:
//  - W[w,t] = A[(t + S_w) mod 256], S_w = (w+1)(w-222)/2
//  - A = conv(gauss, box)/max is ~0 outside a ~40-wide arc (for alpha=0.5):
//    truncate the t-loop to the support (found on device, chunked fallback).
//  - corr_cd = (S_cd - m_c m_d/T) * dinv_c * dinv_d  (the 1/(T-1) cancels)

#define T_LEN 256
#define C_DIM 64
#define NWIN  224
#define B_DIM 16

__device__ float g_A[256];
__device__ int   g_ilo;
__device__ int   g_keff;

// ---------------------------------------------------------------------------
// Prep: A[t] from win_alpha; then scan the support {i : A[i] > 1e-6}.
// ---------------------------------------------------------------------------
__global__ void prep_kernel(const float* __restrict__ alpha) {
    __shared__ float gw[256];
    __shared__ float Ac[511];
    __shared__ float red[64];
    __shared__ float s_max;
    int tid = threadIdx.x;  // 512 threads

    float a = alpha[0];
    float inv = 1.0f / (2.0f * a * a);
    if (tid < 256) {
        float d = (float)tid - 128.0f;
        gw[tid] = expf(-d * d) * inv;
    }
    __syncthreads();
    if (tid < 511) {
        // conv(gw, box)[n] = sum_{k=n-143}^{n-112} gw[k]
        int lo = tid - 143; if (lo < 0)   lo = 0;
        int hi = tid - 112; if (hi > 255) hi = 255;
        float s = 0.0f;
        for (int k = lo; k <= hi; k++) s += gw[k];
        Ac[tid] = s;
    }
    __syncthreads();
    if (tid < 64) {
        float m = 0.0f;
        for (int n = tid; n < 511; n += 64) m = fmaxf(m, Ac[n]);
        red[tid] = m;
    }
    __syncthreads();
    if (tid == 0) {
        float m = 0.0f;
        #pragma unroll
        for (int n = 0; n < 64; n++) m = fmaxf(m, red[n]);
        s_max = m;
    }
    __syncthreads();
    if (tid < 256) g_A[tid] = Ac[128 + tid] / s_max;
    __syncthreads();
    if (tid == 0) {
        // support scan (A unimodal -> contiguous above-threshold arc)
        const float tau = 1e-6f;
        int lo = 0, hi = 255;
        while (lo < 255 && g_A[lo] <= tau) lo++;
        while (hi > lo  && g_A[hi] <= tau) hi--;
        g_ilo  = lo;
        g_keff = hi - lo + 1;
    }
}

// ---------------------------------------------------------------------------
// Main: one 64-thread CTA per (w, b). Each thread owns one 8x8 (c,d) tile and
// the FULL (truncated) K reduction -> no cross-thread partials.
// smem y[64][64] holds up to 64 weighted rows; reused as the cov tile after.
// ---------------------------------------------------------------------------
__global__ __launch_bounds__(64) void corr_kernel(const float* __restrict__ x,
                                                  float* __restrict__ out) {
    __shared__ float y[64][64];     // 16 KB, reused for cov tile
    __shared__ float mcol[64];
    __shared__ float dinv[64];

    const int w   = blockIdx.x;
    const int b   = blockIdx.y;
    const int tid = threadIdx.x;

    // cumulative roll: S_w = (w+1)(w-222)/2 (product always even -> exact)
    int s = ((w + 1) * (w - 222)) / 2;
    int smod = ((s % 256) + 256) & 255;

    const int ilo  = g_ilo;
    const int keff = g_keff;

    const int ci0 = (tid & 7) << 3;
    const int dj0 = (tid >> 3) << 3;
    const float* xb = x + ((size_t)b << 14);

    float acc[64];
    #pragma unroll
    for (int k = 0; k < 64; k++) acc[k] = 0.0f;
    float mc = 0.0f;

    for (int base = 0; base < keff; base += 64) {
        int jn  = keff - base; if (jn > 64) jn = 64;
        int jnp = (jn + 3) & ~3;            // zero-padded row count (mult of 4)

        __syncthreads();                    // protect y from prior-chunk readers

        // ---- build y rows: 4 rows per pass, coalesced 256B per row ----
        #pragma unroll
        for (int pass = 0; pass < 16; pass++) {
            int j = (pass << 2) + (tid >> 4);
            if (j < jnp) {
                int c4 = (tid & 15) << 2;
                float4 v = make_float4(0.f, 0.f, 0.f, 0.f);
                if (j < jn) {
                    int i = ilo + base + j;
                    int t = (i - smod) & 255;
                    float aw = g_A[i];
                    v = *(const float4*)(xb + (t << 6) + c4);
                    v.x *= aw; v.y *= aw; v.z *= aw; v.w *= aw;
                }
                *(float4*)(&y[j][c4]) = v;
            }
        }
        __syncthreads();

        // ---- column sum (thread tid owns column tid) ----
        #pragma unroll 4
        for (int j = 0; j < jn; j++) mc += y[j][tid];

        // ---- Gram accumulation over this chunk ----
        #pragma unroll 4
        for (int j = 0; j < jnp; j++) {
            const float* row = y[j];
            float4 a0 = *(const float4*)(row + ci0);
            float4 a1 = *(const float4*)(row + ci0 + 4);
            float4 b0 = *(const float4*)(row + dj0);
            float4 b1 = *(const float4*)(row + dj0 + 4);
            float ac[8] = {a0.x, a0.y, a0.z, a0.w, a1.x, a1.y, a1.z, a1.w};
            float bd[8] = {b0.x, b0.y, b0.z, b0.w, b1.x, b1.y, b1.z, b1.w};
            #pragma unroll
            for (int ci = 0; ci < 8; ci++)
                #pragma unroll
                for (int dj = 0; dj < 8; dj++)
                    acc[ci * 8 + dj] = fmaf(ac[ci], bd[dj], acc[ci * 8 + dj]);
        }
    }

    mcol[tid] = mc;
    __syncthreads();                        // gram done; y reusable; mcol ready

    // ---- publish centered second moment into y (cov up to the /255 scale) ----
    const float inv256 = 1.0f / 256.0f;
    {
        float mrow[8], mcl[8];
        #pragma unroll
        for (int k = 0; k < 8; k++) { mrow[k] = mcol[ci0 + k]; mcl[k] = mcol[dj0 + k]; }
        #pragma unroll
        for (int ci = 0; ci < 8; ci++) {
            #pragma unroll
            for (int dj = 0; dj < 8; dj++)
                y[ci0 + ci][dj0 + dj] = acc[ci * 8 + dj] - mrow[ci] * mcl[dj] * inv256;
        }
    }
    __syncthreads();

    dinv[tid] = rsqrtf(y[tid][tid]);        // scale cancels in corr
    __syncthreads();

    // ---- normalize, clip, write (coalesced float4, 1KB per pass) ----
    float* ob = out + (((size_t)(b * NWIN + w)) << 12);
    #pragma unroll
    for (int rr = 0; rr < 16; rr++) {
        int r  = (rr << 2) + (tid >> 4);
        int c4 = (tid & 15) << 2;
        float dr_ = dinv[r];
        float4 v;
        v.x = y[r][c4 + 0] * dr_ * dinv[c4 + 0];
        v.y = y[r][c4 + 1] * dr_ * dinv[c4 + 1];
        v.z = y[r][c4 + 2] * dr_ * dinv[c4 + 2];
        v.w = y[r][c4 + 3] * dr_ * dinv[c4 + 3];
        v.x = fminf(1.0f, fmaxf(-1.0f, v.x));
        v.y = fminf(1.0f, fmaxf(-1.0f, v.y));
        v.z = fminf(1.0f, fmaxf(-1.0f, v.z));
        v.w = fminf(1.0f, fmaxf(-1.0f, v.w));
        *(float4*)(ob + (r << 6) + c4) = v;
    }
}

// ---------------------------------------------------------------------------
extern "C" void kernel_launch(void* const* d_in, const int* in_sizes, int n_in,
                              void* d_out, int out_size) {
    const float* x     = (const float*)d_in[0];   // (16, 256, 64) fp32
    const float* alpha = (const float*)d_in[1];   // (1,) fp32
    float* out = (float*)d_out;                   // (16, 224, 64, 64) fp32

    prep_kernel<<<1, 512>>>(alpha);
    dim3 grid(NWIN, B_DIM);
    corr_kernel<<<grid, 64>>>(x, out);
}

// round 7
// speedup vs baseline: 8.6728x; 1.2724x over previous
#include <cuda_runtime.h>
#include <cstdint>

// SlidingGaussianWindow1d: out[b,w,c,d] = clip(corrcoef_t of x[b,t,:] * W[w,t])
// B=16, T=256, C=64, NWIN=224.
//
// Identities:
//  - W[w,t] = A[(t + S_w) mod 256], S_w = (w+1)(w-222)/2
//  - A = conv(gauss, box)/max ~0 outside a ~40-wide arc: truncate t-loop to
//    the support (found on device; chunked fallback for wide alpha).
//  - corr_cd = (S_cd - m_c m_d/T) * dinv_c * dinv_d (1/(T-1) cancels)
//
// R7: broadcast strip tiling. Warp w owns c-rows [16w,16w+16) x all 64 d.
// a-slice loads are uniform-address (HW broadcast, 1 wavefront); b is a
// per-lane float2. Epilogue writes straight from registers.

#define T_LEN 256
#define C_DIM 64
#define NWIN  224
#define B_DIM 16

__device__ float g_A[256];
__device__ int   g_ilo;
__device__ int   g_keff;

// ---------------------------------------------------------------------------
// Prep: A[t] from win_alpha; parallel support scan {i : A[i] > 1e-6}.
// ---------------------------------------------------------------------------
__global__ void prep_kernel(const float* __restrict__ alpha) {
    __shared__ float gw[256];
    __shared__ float Ac[511];
    __shared__ float red[64];
    __shared__ float sA[256];
    __shared__ float s_max;
    __shared__ unsigned int masks[8];
    int tid = threadIdx.x;  // 512 threads

    float a = alpha[0];
    float inv = 1.0f / (2.0f * a * a);
    if (tid < 256) {
        float d = (float)tid - 128.0f;
        gw[tid] = expf(-d * d) * inv;
    }
    __syncthreads();
    if (tid < 511) {
        // conv(gw, box)[n] = sum_{k=n-143}^{n-112} gw[k]
        int lo = tid - 143; if (lo < 0)   lo = 0;
        int hi = tid - 112; if (hi > 255) hi = 255;
        float s = 0.0f;
        for (int k = lo; k <= hi; k++) s += gw[k];
        Ac[tid] = s;
    }
    __syncthreads();
    if (tid < 64) {
        float m = 0.0f;
        for (int n = tid; n < 511; n += 64) m = fmaxf(m, Ac[n]);
        red[tid] = m;
    }
    __syncthreads();
    if (tid == 0) {
        float m = 0.0f;
        #pragma unroll
        for (int n = 0; n < 64; n++) m = fmaxf(m, red[n]);
        s_max = m;
    }
    __syncthreads();
    if (tid < 256) {
        float v = Ac[128 + tid] / s_max;
        sA[tid] = v;
        g_A[tid] = v;
    }
    __syncthreads();
    if (tid < 256) {  // warps 0..7 full
        unsigned int m = __ballot_sync(0xFFFFFFFFu, sA[tid] > 1e-6f);
        if ((tid & 31) == 0) masks[tid >> 5] = m;
    }
    __syncthreads();
    if (tid == 0) {
        int lo = 0, hi = 255;
        for (int k = 0; k < 8; k++)
            if (masks[k]) { lo = k * 32 + __ffs(masks[k]) - 1; break; }
        for (int k = 7; k >= 0; k--)
            if (masks[k]) { hi = k * 32 + 31 - __clz(masks[k]); break; }
        g_ilo  = lo;
        g_keff = hi - lo + 1;
    }
}

// ---------------------------------------------------------------------------
// Main: 128 threads per (w, b). Warp wid: c-rows [16wid,16wid+16); lane owns
// d-cols {2l, 2l+1}. acc[32] in regs. y[64][64] smem holds weighted rows.
// ---------------------------------------------------------------------------
__global__ __launch_bounds__(128) void corr_kernel(const float* __restrict__ x,
                                                   float* __restrict__ out) {
    __shared__ float y[64][64];          // 16 KB
    __shared__ float mpart[2][64];
    __shared__ float mcol[64];
    __shared__ float dinv[64];

    const int w    = blockIdx.x;
    const int b    = blockIdx.y;
    const int tid  = threadIdx.x;
    const int wid  = tid >> 5;
    const int lane = tid & 31;

    int s = ((w + 1) * (w - 222)) / 2;   // cumulative roll (even product, exact)
    int smod = ((s % 256) + 256) & 255;

    const int ilo  = g_ilo;
    const int keff = g_keff;

    const float* xb = x + ((size_t)b << 14);
    const int c0 = wid << 4;             // this warp's 16 c-rows
    const int d0 = lane << 1;            // this lane's 2 d-cols

    float acc[32];
    #pragma unroll
    for (int k = 0; k < 32; k++) acc[k] = 0.0f;
    float mc = 0.0f;                     // partial col sum: col tid&63, t%2==tid>>6

    for (int base = 0; base < keff; base += 64) {
        int jn  = keff - base; if (jn > 64) jn = 64;
        int jnp = (jn + 3) & ~3;

        __syncthreads();                 // protect y from prior-chunk readers

        // ---- build: 8 rows per pass, coalesced 256B rows ----
        for (int pass = 0; (pass << 3) < jnp; pass++) {
            int j = (pass << 3) + (tid >> 4);
            if (j < jnp) {
                int c4 = (tid & 15) << 2;
                float4 v = make_float4(0.f, 0.f, 0.f, 0.f);
                if (j < jn) {
                    int i = ilo + base + j;
                    int t = (i - smod) & 255;
                    float aw = g_A[i];
                    v = *(const float4*)(xb + (t << 6) + c4);
                    v.x *= aw; v.y *= aw; v.z *= aw; v.w *= aw;
                }
                *(float4*)(&y[j][c4]) = v;
            }
        }
        __syncthreads();

        // ---- column partial sums (2-way split over t) ----
        {
            int col = tid & 63, h = tid >> 6;
            for (int t = h; t < jn; t += 2) mc += y[t][col];
        }

        // ---- Gram: 16x2 tile per thread, broadcast a-slice ----
        #pragma unroll 4
        for (int j = 0; j < jnp; j++) {
            const float* row = y[j];
            float4 A0 = *(const float4*)(row + c0);
            float4 A1 = *(const float4*)(row + c0 + 4);
            float4 A2 = *(const float4*)(row + c0 + 8);
            float4 A3 = *(const float4*)(row + c0 + 12);
            float2 bv = *(const float2*)(row + d0);
            float av[16] = {A0.x, A0.y, A0.z, A0.w, A1.x, A1.y, A1.z, A1.w,
                            A2.x, A2.y, A2.z, A2.w, A3.x, A3.y, A3.z, A3.w};
            #pragma unroll
            for (int i = 0; i < 16; i++) {
                acc[i * 2 + 0] = fmaf(av[i], bv.x, acc[i * 2 + 0]);
                acc[i * 2 + 1] = fmaf(av[i], bv.y, acc[i * 2 + 1]);
            }
        }
    }

    // ---- combine column sums ----
    mpart[tid >> 6][tid & 63] = mc;
    __syncthreads();
    if (tid < 64) mcol[tid] = mpart[0][tid] + mpart[1][tid];
    __syncthreads();

    // ---- diagonal -> dinv (owner lanes: d0 within this warp's c-range) ----
    const float inv256 = 1.0f / 256.0f;
    {
        int ii = d0 - c0;                // even when in range
        if (ii >= 0 && ii < 16) {
            float m0 = mcol[d0], m1 = mcol[d0 + 1];
            dinv[d0]     = rsqrtf(acc[ii * 2]           - m0 * m0 * inv256);
            dinv[d0 + 1] = rsqrtf(acc[(ii + 1) * 2 + 1] - m1 * m1 * inv256);
        }
    }
    __syncthreads();

    // ---- normalize, clip, write straight from registers ----
    float md0 = mcol[d0], md1 = mcol[d0 + 1];
    float dd0 = dinv[d0], dd1 = dinv[d0 + 1];
    float* ob = out + (((size_t)(b * NWIN + w)) << 12) + d0;
    #pragma unroll
    for (int i = 0; i < 16; i++) {
        int c = c0 + i;
        float mcv = mcol[c] * inv256;
        float dcv = dinv[c];
        float2 v;
        v.x = (acc[i * 2 + 0] - mcv * md0) * dcv * dd0;
        v.y = (acc[i * 2 + 1] - mcv * md1) * dcv * dd1;
        v.x = fminf(1.0f, fmaxf(-1.0f, v.x));
        v.y = fminf(1.0f, fmaxf(-1.0f, v.y));
        *(float2*)(ob + (c << 6)) = v;   // warp: 256B contiguous per i
    }
}

// ---------------------------------------------------------------------------
extern "C" void kernel_launch(void* const* d_in, const int* in_sizes, int n_in,
                              void* d_out, int out_size) {
    const float* x     = (const float*)d_in[0];   // (16, 256, 64) fp32
    const float* alpha = (const float*)d_in[1];   // (1,) fp32
    float* out = (float*)d_out;                   // (16, 224, 64, 64) fp32

    prep_kernel<<<1, 512>>>(alpha);
    dim3 grid(NWIN, B_DIM);
    corr_kernel<<<grid, 128>>>(x, out);
}

// round 8
// speedup vs baseline: 11.0772x; 1.2772x over previous
#include <cuda_runtime.h>
#include <cstdint>

// SlidingGaussianWindow1d: out[b,w,c,d] = clip(corrcoef_t of x[b,t,:] * W[w,t])
// B=16, T=256, C=64, NWIN=224.
//
// Identities:
//  - W[w,t] = A[(t + S_w) mod 256], S_w = (w+1)(w-222)/2
//  - A = conv(gauss, box)/max ~0 outside a ~40-wide arc: truncate t-loop to
//    the support (found on device; chunked fallback for wide alpha).
//  - corr_cd = (S_cd - m_c m_d/T) * dinv_c * dinv_d (1/(T-1) cancels)
//
// R8: packed fma.rn.f32x2 mainloop (2 FMA/inst), column sums folded into the
// gram loop as one add.rn.f32x2 per j (computed redundantly per warp).

#define T_LEN 256
#define C_DIM 64
#define NWIN  224
#define B_DIM 16

typedef unsigned long long ull;

__device__ float g_A[256];
__device__ int   g_ilo;
__device__ int   g_keff;

// ---------------------------------------------------------------------------
// Prep: A[t] from win_alpha; parallel support scan {i : A[i] > 1e-6}.
// ---------------------------------------------------------------------------
__global__ void prep_kernel(const float* __restrict__ alpha) {
    __shared__ float gw[256];
    __shared__ float Ac[511];
    __shared__ float red[64];
    __shared__ float sA[256];
    __shared__ float s_max;
    __shared__ unsigned int masks[8];
    int tid = threadIdx.x;  // 512 threads

    float a = alpha[0];
    float inv = 1.0f / (2.0f * a * a);
    if (tid < 256) {
        float d = (float)tid - 128.0f;
        gw[tid] = expf(-d * d) * inv;
    }
    __syncthreads();
    if (tid < 511) {
        int lo = tid - 143; if (lo < 0)   lo = 0;
        int hi = tid - 112; if (hi > 255) hi = 255;
        float s = 0.0f;
        for (int k = lo; k <= hi; k++) s += gw[k];
        Ac[tid] = s;
    }
    __syncthreads();
    if (tid < 64) {
        float m = 0.0f;
        for (int n = tid; n < 511; n += 64) m = fmaxf(m, Ac[n]);
        red[tid] = m;
    }
    __syncthreads();
    if (tid == 0) {
        float m = 0.0f;
        #pragma unroll
        for (int n = 0; n < 64; n++) m = fmaxf(m, red[n]);
        s_max = m;
    }
    __syncthreads();
    if (tid < 256) {
        float v = Ac[128 + tid] / s_max;
        sA[tid] = v;
        g_A[tid] = v;
    }
    __syncthreads();
    if (tid < 256) {
        unsigned int m = __ballot_sync(0xFFFFFFFFu, sA[tid] > 1e-6f);
        if ((tid & 31) == 0) masks[tid >> 5] = m;
    }
    __syncthreads();
    if (tid == 0) {
        int lo = 0, hi = 255;
        for (int k = 0; k < 8; k++)
            if (masks[k]) { lo = k * 32 + __ffs(masks[k]) - 1; break; }
        for (int k = 7; k >= 0; k--)
            if (masks[k]) { hi = k * 32 + 31 - __clz(masks[k]); break; }
        g_ilo  = lo;
        g_keff = hi - lo + 1;
    }
}

// ---------------------------------------------------------------------------
// Main: 128 threads per (w, b). Warp wid: c-rows [16wid,16wid+16); lane owns
// d-cols {2l, 2l+1}. Accumulators are 16 packed f32x2 (i-pairs x 2 d).
// ---------------------------------------------------------------------------
__global__ __launch_bounds__(128) void corr_kernel(const float* __restrict__ x,
                                                   float* __restrict__ out) {
    __shared__ float y[64][64];          // 16 KB
    __shared__ float mcol[64];
    __shared__ float dinv[64];

    const int w    = blockIdx.x;
    const int b    = blockIdx.y;
    const int tid  = threadIdx.x;
    const int wid  = tid >> 5;
    const int lane = tid & 31;

    int s = ((w + 1) * (w - 222)) / 2;   // cumulative roll (even product, exact)
    int smod = ((s % 256) + 256) & 255;

    const int ilo  = g_ilo;
    const int keff = g_keff;

    const float* xb = x + ((size_t)b << 14);
    const int c0 = wid << 4;             // this warp's 16 c-rows
    const int d0 = lane << 1;            // this lane's 2 d-cols

    ull acc2[16];                        // acc2[k*2+dd]: i=2k(lo),2k+1(hi); d=d0+dd
    #pragma unroll
    for (int k = 0; k < 16; k++) acc2[k] = 0ull;
    ull msum2 = 0ull;                    // packed (sum_d0, sum_d0+1)

    const uint32_t ybase = (uint32_t)__cvta_generic_to_shared(&y[0][0]);

    for (int base = 0; base < keff; base += 64) {
        int jn  = keff - base; if (jn > 64) jn = 64;
        int jnp = (jn + 3) & ~3;

        __syncthreads();                 // protect y from prior-chunk readers

        // ---- build: 8 rows per pass, coalesced 256B rows (zeros pad to jnp) ----
        for (int pass = 0; (pass << 3) < jnp; pass++) {
            int j = (pass << 3) + (tid >> 4);
            if (j < jnp) {
                int c4 = (tid & 15) << 2;
                float4 v = make_float4(0.f, 0.f, 0.f, 0.f);
                if (j < jn) {
                    int i = ilo + base + j;
                    int t = (i - smod) & 255;
                    float aw = g_A[i];
                    v = *(const float4*)(xb + (t << 6) + c4);
                    v.x *= aw; v.y *= aw; v.z *= aw; v.w *= aw;
                }
                *(float4*)(&y[j][c4]) = v;
            }
        }
        __syncthreads();

        // ---- Gram: packed f32x2, broadcast a-slice, fused column sums ----
        uint32_t arow = ybase + (c0 << 2);
        uint32_t brow = ybase + (d0 << 2);
        #pragma unroll 4
        for (int j = 0; j < jnp; j++, arow += 256, brow += 256) {
            ull a0, a1, a2, a3, a4, a5, a6, a7, bv, blo, bhi;
            asm volatile("ld.shared.v2.u64 {%0,%1}, [%2];" : "=l"(a0), "=l"(a1) : "r"(arow));
            asm volatile("ld.shared.v2.u64 {%0,%1}, [%2];" : "=l"(a2), "=l"(a3) : "r"(arow + 16));
            asm volatile("ld.shared.v2.u64 {%0,%1}, [%2];" : "=l"(a4), "=l"(a5) : "r"(arow + 32));
            asm volatile("ld.shared.v2.u64 {%0,%1}, [%2];" : "=l"(a6), "=l"(a7) : "r"(arow + 48));
            asm volatile("ld.shared.b64 %0, [%1];" : "=l"(bv) : "r"(brow));
            uint32_t bx, by;
            asm("mov.b64 {%0,%1}, %2;" : "=r"(bx), "=r"(by) : "l"(bv));
            asm("mov.b64 %0, {%1,%1};" : "=l"(blo) : "r"(bx));
            asm("mov.b64 %0, {%1,%1};" : "=l"(bhi) : "r"(by));
            asm("add.rn.f32x2 %0, %0, %1;" : "+l"(msum2) : "l"(bv));
            asm("fma.rn.f32x2 %0, %1, %2, %0;" : "+l"(acc2[0])  : "l"(a0), "l"(blo));
            asm("fma.rn.f32x2 %0, %1, %2, %0;" : "+l"(acc2[1])  : "l"(a0), "l"(bhi));
            asm("fma.rn.f32x2 %0, %1, %2, %0;" : "+l"(acc2[2])  : "l"(a1), "l"(blo));
            asm("fma.rn.f32x2 %0, %1, %2, %0;" : "+l"(acc2[3])  : "l"(a1), "l"(bhi));
            asm("fma.rn.f32x2 %0, %1, %2, %0;" : "+l"(acc2[4])  : "l"(a2), "l"(blo));
            asm("fma.rn.f32x2 %0, %1, %2, %0;" : "+l"(acc2[5])  : "l"(a2), "l"(bhi));
            asm("fma.rn.f32x2 %0, %1, %2, %0;" : "+l"(acc2[6])  : "l"(a3), "l"(blo));
            asm("fma.rn.f32x2 %0, %1, %2, %0;" : "+l"(acc2[7])  : "l"(a3), "l"(bhi));
            asm("fma.rn.f32x2 %0, %1, %2, %0;" : "+l"(acc2[8])  : "l"(a4), "l"(blo));
            asm("fma.rn.f32x2 %0, %1, %2, %0;" : "+l"(acc2[9])  : "l"(a4), "l"(bhi));
            asm("fma.rn.f32x2 %0, %1, %2, %0;" : "+l"(acc2[10]) : "l"(a5), "l"(blo));
            asm("fma.rn.f32x2 %0, %1, %2, %0;" : "+l"(acc2[11]) : "l"(a5), "l"(bhi));
            asm("fma.rn.f32x2 %0, %1, %2, %0;" : "+l"(acc2[12]) : "l"(a6), "l"(blo));
            asm("fma.rn.f32x2 %0, %1, %2, %0;" : "+l"(acc2[13]) : "l"(a6), "l"(bhi));
            asm("fma.rn.f32x2 %0, %1, %2, %0;" : "+l"(acc2[14]) : "l"(a7), "l"(blo));
            asm("fma.rn.f32x2 %0, %1, %2, %0;" : "+l"(acc2[15]) : "l"(a7), "l"(bhi));
        }
    }

    // ---- unpack accumulators: accf[i*2+dd] = S(c0+i, d0+dd) ----
    float accf[32];
    #pragma unroll
    for (int k = 0; k < 8; k++) {
        float l0, h0, l1, h1;
        asm("mov.b64 {%0,%1}, %2;" : "=f"(l0), "=f"(h0) : "l"(acc2[k * 2 + 0]));
        asm("mov.b64 {%0,%1}, %2;" : "=f"(l1), "=f"(h1) : "l"(acc2[k * 2 + 1]));
        accf[(2 * k) * 2 + 0] = l0;  accf[(2 * k + 1) * 2 + 0] = h0;
        accf[(2 * k) * 2 + 1] = l1;  accf[(2 * k + 1) * 2 + 1] = h1;
    }

    // ---- column sums: every warp computed all 64; warp 0 publishes ----
    if (wid == 0) {
        float mx, my;
        asm("mov.b64 {%0,%1}, %2;" : "=f"(mx), "=f"(my) : "l"(msum2));
        mcol[d0] = mx;
        mcol[d0 + 1] = my;
    }
    __syncthreads();

    // ---- diagonal -> dinv (owner: warp with c0 <= d0 < c0+16) ----
    const float inv256 = 1.0f / 256.0f;
    {
        int ii = d0 - c0;                // even when in range
        if (ii >= 0 && ii < 16) {
            float m0 = mcol[d0], m1 = mcol[d0 + 1];
            dinv[d0]     = rsqrtf(accf[ii * 2]           - m0 * m0 * inv256);
            dinv[d0 + 1] = rsqrtf(accf[(ii + 1) * 2 + 1] - m1 * m1 * inv256);
        }
    }
    __syncthreads();

    // ---- normalize, clip, write straight from registers ----
    float md0 = mcol[d0], md1 = mcol[d0 + 1];
    float dd0 = dinv[d0], dd1 = dinv[d0 + 1];
    float* ob = out + (((size_t)(b * NWIN + w)) << 12) + d0;
    #pragma unroll
    for (int i = 0; i < 16; i++) {
        int c = c0 + i;
        float mcv = mcol[c] * inv256;
        float dcv = dinv[c];
        float2 v;
        v.x = (accf[i * 2 + 0] - mcv * md0) * dcv * dd0;
        v.y = (accf[i * 2 + 1] - mcv * md1) * dcv * dd1;
        v.x = fminf(1.0f, fmaxf(-1.0f, v.x));
        v.y = fminf(1.0f, fmaxf(-1.0f, v.y));
        *(float2*)(ob + (c << 6)) = v;   // warp: 256B contiguous per i
    }
}

// ---------------------------------------------------------------------------
extern "C" void kernel_launch(void* const* d_in, const int* in_sizes, int n_in,
                              void* d_out, int out_size) {
    const float* x     = (const float*)d_in[0];   // (16, 256, 64) fp32
    const float* alpha = (const float*)d_in[1];   // (1,) fp32
    float* out = (float*)d_out;                   // (16, 224, 64, 64) fp32

    prep_kernel<<<1, 512>>>(alpha);
    dim3 grid(NWIN, B_DIM);
    corr_kernel<<<grid, 128>>>(x, out);
}